// round 5
// baseline (speedup 1.0000x reference)
#include <cuda_runtime.h>
#include <cuda_fp16.h>

// OhemMSELoss: loss = w*(p-t)^2 / 2^25 over N=2^25; mean of top-k (k=2^18).
// K1: stream inputs -> fp16 unnormalized loss scratch (64 MiB, L2-resident),
//     per-16-elem group max (4 MB skip index), 1/64-sampled coarse histogram.
// K2: conservative threshold T0 from sample (~9-sigma margin).
// K3: scan group-max index; only groups with max >= T0 (~13%) are visited;
//     exact 65536-bin histogram of candidates (global atomics, ~300K total).
// K4: fused tail (1 block, all fp32): 64K-bin suffix scan -> exact top-k mean,
//     then zero the dirty histogram range. No FP64 anywhere (sm_103a FP64 trap).

#define N_ELEM   33554432
#define N16      (N_ELEM / 16)      // 2097152 groups of 16 elements
#define NG4      (N16 / 8)          // 262144 uint4 units of the gmax index
#define K_KEPT   262144u
#define MARGIN   40960u
#define NSB      4096               // sampled-hist bins (half bits >> 4)
#define NREP     8                  // replicas to spread hot-bin atomics

static __device__ __half         g_lossh[N_ELEM];     // 64 MiB (fits L2)
static __device__ unsigned short g_gmax[N16];         // 4 MiB group-max index
static __device__ unsigned       g_shist[NREP][NSB];  // zero-init; cleaned by K2
static __device__ unsigned       g_hist64[65536];     // zero-init; cleaned by K4
static __device__ unsigned       g_T0;

__device__ __forceinline__ float bin_valf(int b) {
    return __half2float(__ushort_as_half((unsigned short)b));
}

// ---------------------------------------------------------------- K1: loss + scratch + gmax + sampled hist
__global__ __launch_bounds__(256) void k_loss(
    const float4* __restrict__ p,
    const float4* __restrict__ t,
    const float4* __restrict__ w)
{
    uint4* out = reinterpret_cast<uint4*>(g_lossh);
    unsigned* hist = g_shist[blockIdx.x & (NREP - 1)];
    const int T = gridDim.x * blockDim.x;

    for (int u = blockIdx.x * blockDim.x + threadIdx.x; u < N16; u += T) {
        const int b = 4 * u;
        // 12 independent LDG.128 in flight; evict-first keeps L2 for scratch
        float4 p0 = __ldcs(p + b),     p1 = __ldcs(p + b + 1);
        float4 p2 = __ldcs(p + b + 2), p3 = __ldcs(p + b + 3);
        float4 t0 = __ldcs(t + b),     t1 = __ldcs(t + b + 1);
        float4 t2 = __ldcs(t + b + 2), t3 = __ldcs(t + b + 3);
        float4 w0 = __ldcs(w + b),     w1 = __ldcs(w + b + 1);
        float4 w2 = __ldcs(w + b + 2), w3 = __ldcs(w + b + 3);

        uint4 A, B;
        {
            float a0 = p0.x-t0.x, a1 = p0.y-t0.y, a2 = p0.z-t0.z, a3 = p0.w-t0.w;
            float c0 = p1.x-t1.x, c1 = p1.y-t1.y, c2 = p1.z-t1.z, c3 = p1.w-t1.w;
            __half2 h0 = __floats2half2_rn(w0.x*a0*a0, w0.y*a1*a1);
            __half2 h1 = __floats2half2_rn(w0.z*a2*a2, w0.w*a3*a3);
            __half2 h2 = __floats2half2_rn(w1.x*c0*c0, w1.y*c1*c1);
            __half2 h3 = __floats2half2_rn(w1.z*c2*c2, w1.w*c3*c3);
            A.x = *reinterpret_cast<unsigned*>(&h0);
            A.y = *reinterpret_cast<unsigned*>(&h1);
            A.z = *reinterpret_cast<unsigned*>(&h2);
            A.w = *reinterpret_cast<unsigned*>(&h3);
        }
        {
            float a0 = p2.x-t2.x, a1 = p2.y-t2.y, a2 = p2.z-t2.z, a3 = p2.w-t2.w;
            float c0 = p3.x-t3.x, c1 = p3.y-t3.y, c2 = p3.z-t3.z, c3 = p3.w-t3.w;
            __half2 h0 = __floats2half2_rn(w2.x*a0*a0, w2.y*a1*a1);
            __half2 h1 = __floats2half2_rn(w2.z*a2*a2, w2.w*a3*a3);
            __half2 h2 = __floats2half2_rn(w3.x*c0*c0, w3.y*c1*c1);
            __half2 h3 = __floats2half2_rn(w3.z*c2*c2, w3.w*c3*c3);
            B.x = *reinterpret_cast<unsigned*>(&h0);
            B.y = *reinterpret_cast<unsigned*>(&h1);
            B.z = *reinterpret_cast<unsigned*>(&h2);
            B.w = *reinterpret_cast<unsigned*>(&h3);
        }
        out[2*u]     = A;
        out[2*u + 1] = B;

        // group max over 16 halves (bit-monotone for non-negative fp16)
        unsigned m = __vmaxu2(__vmaxu2(__vmaxu2(A.x, A.y), __vmaxu2(A.z, A.w)),
                              __vmaxu2(__vmaxu2(B.x, B.y), __vmaxu2(B.z, B.w)));
        unsigned hm = max(m & 0xFFFFu, m >> 16);
        g_gmax[u] = (unsigned short)hm;

        if ((u & 3) == 0) atomicAdd(&hist[(A.x & 0xFFFFu) >> 4], 1u);  // 1/64 sample
    }
}

// ---------------------------------------------------------------- K2: conservative threshold from sample
__global__ __launch_bounds__(1024) void k_select() {
    __shared__ unsigned ssum[1024];
    const int t = threadIdx.x;

    unsigned b0 = 0, b1 = 0, b2 = 0, b3 = 0;
    #pragma unroll
    for (int r = 0; r < NREP; r++) {
        uint4 v = reinterpret_cast<const uint4*>(g_shist[r])[t];
        b0 += v.x; b1 += v.y; b2 += v.z; b3 += v.w;
    }
    #pragma unroll
    for (int r = 0; r < NREP; r++)
        reinterpret_cast<uint4*>(g_shist[r])[t] = make_uint4(0, 0, 0, 0);

    ssum[t] = b0 + b1 + b2 + b3;
    __syncthreads();
    for (int d = 1; d < 1024; d <<= 1) {
        unsigned v = ssum[t];
        if (t + d < 1024) v += ssum[t + d];
        __syncthreads();
        ssum[t] = v;
        __syncthreads();
    }
    const unsigned TGT = (K_KEPT + MARGIN + 63u) / 64u;   // sampled-count target
    unsigned sufnext = (t < 1023) ? ssum[t + 1] : 0u;
    if (ssum[t] >= TGT && sufnext < TGT) {
        unsigned bins[4] = {b0, b1, b2, b3};
        unsigned cum = sufnext;
        unsigned T0 = 0;
        for (int b = 3; b >= 0; b--) {
            cum += bins[b];
            if (cum >= TGT) { T0 = ((unsigned)(t * 4 + b)) << 4; break; }
        }
        g_T0 = T0;
    }
}

// ---------------------------------------------------------------- K3: gmax-guided candidate histogram
__global__ __launch_bounds__(256) void k_scan() {
    const unsigned T0 = g_T0;
    const unsigned TT = T0 | (T0 << 16);
    const uint4* gm = reinterpret_cast<const uint4*>(g_gmax);
    const uint4* in = reinterpret_cast<const uint4*>(g_lossh);
    const int T = gridDim.x * blockDim.x;

    #define PROC_UNIT(v) do {                                                   \
        unsigned _m = __vcmpgeu2(__vmaxu2(__vmaxu2((v).x,(v).y),                \
                                          __vmaxu2((v).z,(v).w)), TT);          \
        if (_m) {                                                               \
            unsigned _h;                                                        \
            _h = (v).x & 0xFFFFu; if (_h >= T0) atomicAdd(&g_hist64[_h], 1u);   \
            _h = (v).x >> 16;     if (_h >= T0) atomicAdd(&g_hist64[_h], 1u);   \
            _h = (v).y & 0xFFFFu; if (_h >= T0) atomicAdd(&g_hist64[_h], 1u);   \
            _h = (v).y >> 16;     if (_h >= T0) atomicAdd(&g_hist64[_h], 1u);   \
            _h = (v).z & 0xFFFFu; if (_h >= T0) atomicAdd(&g_hist64[_h], 1u);   \
            _h = (v).z >> 16;     if (_h >= T0) atomicAdd(&g_hist64[_h], 1u);   \
            _h = (v).w & 0xFFFFu; if (_h >= T0) atomicAdd(&g_hist64[_h], 1u);   \
            _h = (v).w >> 16;     if (_h >= T0) atomicAdd(&g_hist64[_h], 1u);   \
        }                                                                       \
    } while (0)

    #define PROC_GROUP(g) do {                                                  \
        uint4 _a = in[2*(g)], _b = in[2*(g)+1];                                 \
        PROC_UNIT(_a); PROC_UNIT(_b);                                           \
    } while (0)

    #define PROC_GM(mv, idx) do {                                               \
        unsigned _mm = __vmaxu2(__vmaxu2((mv).x,(mv).y), __vmaxu2((mv).z,(mv).w)); \
        if (__vcmpgeu2(_mm, TT)) {                                              \
            int _g = 8*(idx);                                                   \
            if (((mv).x & 0xFFFFu) >= T0) PROC_GROUP(_g + 0);                   \
            if (((mv).x >> 16)     >= T0) PROC_GROUP(_g + 1);                   \
            if (((mv).y & 0xFFFFu) >= T0) PROC_GROUP(_g + 2);                   \
            if (((mv).y >> 16)     >= T0) PROC_GROUP(_g + 3);                   \
            if (((mv).z & 0xFFFFu) >= T0) PROC_GROUP(_g + 4);                   \
            if (((mv).z >> 16)     >= T0) PROC_GROUP(_g + 5);                   \
            if (((mv).w & 0xFFFFu) >= T0) PROC_GROUP(_g + 6);                   \
            if (((mv).w >> 16)     >= T0) PROC_GROUP(_g + 7);                   \
        }                                                                       \
    } while (0)

    for (int i = blockIdx.x * blockDim.x + threadIdx.x; i < NG4; i += 2 * T) {
        const int i2 = i + T;
        uint4 m0 = gm[i];
        uint4 m1;
        const bool h2v = (i2 < NG4);
        if (h2v) m1 = gm[i2];
        PROC_GM(m0, i);
        if (h2v) PROC_GM(m1, i2);
    }
    #undef PROC_GM
    #undef PROC_GROUP
    #undef PROC_UNIT
}

// ---------------------------------------------------------------- K4: fused tail (all fp32, 1 block)
__global__ __launch_bounds__(1024) void k_tail(float* __restrict__ out) {
    __shared__ unsigned sc[1024];
    __shared__ float    sw[1024];
    __shared__ int      s_chunk;
    __shared__ unsigned s_ac;
    __shared__ float    s_aw;
    const int t = threadIdx.x;
    const uint4* h4 = reinterpret_cast<const uint4*>(g_hist64);

    // per-thread: 64 bins via 16 independent uint4 loads (fp32 accumulation)
    unsigned cnt = 0; float ws = 0.0f;
    #pragma unroll
    for (int jj = 0; jj < 16; jj++) {
        uint4 v = h4[t * 16 + jj];
        int b = t * 64 + jj * 4;
        cnt += v.x + v.y + v.z + v.w;
        if (v.x) ws += (float)v.x * bin_valf(b + 0);
        if (v.y) ws += (float)v.y * bin_valf(b + 1);
        if (v.z) ws += (float)v.z * bin_valf(b + 2);
        if (v.w) ws += (float)v.w * bin_valf(b + 3);
    }
    sc[t] = cnt; sw[t] = ws;
    if (t == 0) s_chunk = -1;
    __syncthreads();
    for (int d = 1; d < 1024; d <<= 1) {              // suffix scan
        unsigned c = sc[t]; float x = sw[t];
        if (t + d < 1024) { c += sc[t + d]; x += sw[t + d]; }
        __syncthreads();
        sc[t] = c; sw[t] = x;
        __syncthreads();
    }
    unsigned cn = (t < 1023) ? sc[t + 1] : 0u;
    float    wn = (t < 1023) ? sw[t + 1] : 0.0f;
    if (sc[t] >= K_KEPT && cn < K_KEPT) { s_chunk = t; s_ac = cn; s_aw = wn; }
    __syncthreads();

    const int chunk = s_chunk;
    if (chunk < 0) {                                  // margin failure (~9-sigma; ~never)
        if (t == 0) {
            float acc = sw[0] + (float)(K_KEPT - sc[0]) * bin_valf((int)g_T0);
            out[0] = acc / 8796093022208.0f;          // / 2^43
        }
    } else {
        __syncthreads();
        if (t < 64) {
            unsigned c = g_hist64[chunk * 64 + t];
            sc[t] = c;
            sw[t] = c ? (float)c * bin_valf(chunk * 64 + t) : 0.0f;
        }
        __syncthreads();
        for (int d = 1; d < 64; d <<= 1) {
            unsigned c = 0; float x = 0.0f;
            if (t < 64) { c = sc[t]; x = sw[t]; if (t + d < 64) { c += sc[t + d]; x += sw[t + d]; } }
            __syncthreads();
            if (t < 64) { sc[t] = c; sw[t] = x; }
            __syncthreads();
        }
        if (t < 64) {
            unsigned bn = (t < 63) ? sc[t + 1] : 0u;
            float    bw = (t < 63) ? sw[t + 1] : 0.0f;
            unsigned above = s_ac + bn;
            if (s_ac + sc[t] >= K_KEPT && above < K_KEPT) {
                unsigned r = K_KEPT - above;
                float acc = s_aw + bw + (float)r * bin_valf(chunk * 64 + t);
                out[0] = acc / 8796093022208.0f;      // / (2^25 * 2^18)
            }
        }
    }
    __syncthreads();
    // zero only the dirty histogram range [T0, 65536)
    uint4 z = make_uint4(0, 0, 0, 0);
    for (unsigned idx = (g_T0 >> 2) + t; idx < 16384u; idx += 1024u)
        reinterpret_cast<uint4*>(g_hist64)[idx] = z;
}

// ---------------------------------------------------------------- launch
extern "C" void kernel_launch(void* const* d_in, const int* in_sizes, int n_in,
                              void* d_out, int out_size) {
    const float4* p = (const float4*)d_in[0];   // predict
    const float4* t = (const float4*)d_in[1];   // target
    const float4* w = (const float4*)d_in[2];   // weight
    float* out = (float*)d_out;

    k_loss  <<<1184, 256>>>(p, t, w);
    k_select<<<1, 1024>>>();
    k_scan  <<<592, 256>>>();
    k_tail  <<<1, 1024>>>(out);
}

// round 6
// speedup vs baseline: 1.5848x; 1.5848x over previous
#include <cuda_runtime.h>
#include <cuda_fp16.h>

// OhemMSELoss: loss = w*(p-t)^2 / 2^25 over N=2^25; mean of top-k (k=2^18).
// K1: coalesced stream -> fp16 loss scratch (64 MiB) + per-16-elem group max
//     (4 MB skip index, via 4-lane shfl reduce) + 1/64-sampled histogram.
// K2: conservative threshold T0 from sample (~9-sigma margin).
// K3: scan group-max index; only groups with max >= T0 (~13%) visited;
//     exact 65536-bin histogram of candidates (global atomics, ~300K total).
// K4: fused tail: 256 blocks reduce chunks -> last block (ticket) finalizes,
//     zeroes dirty hist range, resets ticket. All fp32 (sm_103a FP64 is slow).

#define N_ELEM   33554432
#define N4       (N_ELEM / 4)       // 8388608 float4 per stream
#define N16      (N_ELEM / 16)      // 2097152 groups
#define NG4      (N16 / 8)          // 262144 uint4 units of gmax index
#define K_KEPT   262144u
#define MARGIN   40960u
#define NSB      4096
#define NREP     8

static __device__ __half         g_lossh[N_ELEM];     // 64 MiB (fits L2)
static __device__ unsigned short g_gmax[N16];         // 4 MiB skip index
static __device__ unsigned       g_shist[NREP][NSB];  // zero-init; cleaned by K2
static __device__ unsigned       g_hist64[65536];     // zero-init; cleaned by K4
static __device__ unsigned       g_T0;
static __device__ unsigned       g_ccnt[256];
static __device__ float          g_cwt[256];
static __device__ unsigned       g_ticket;            // zero-init; reset by K4

__device__ __forceinline__ float bin_valf(int b) {
    return __half2float(__ushort_as_half((unsigned short)b));
}

// ---------------------------------------------------------------- K1
// grid MUST be 1024 x 256: N4 / (4*T) == 8 exactly -> uniform trip count
// (shfl-safe), lane-consecutive float4 indices -> perfect coalescing.
__global__ __launch_bounds__(256) void k_loss(
    const float4* __restrict__ p,
    const float4* __restrict__ t,
    const float4* __restrict__ w)
{
    uint2* out = reinterpret_cast<uint2*>(g_lossh);
    unsigned* hist = g_shist[blockIdx.x & (NREP - 1)];
    const int T = gridDim.x * blockDim.x;             // 262144
    const int lane = threadIdx.x & 31;
    const bool qlead = ((lane & 3) == 0);
    const bool samp  = ((threadIdx.x & 15) == 0);     // 1/64-element sampling

    for (int f = blockIdx.x * blockDim.x + threadIdx.x; f < N4; f += 4 * T) {
        const int f1 = f + T, f2 = f + 2 * T, f3 = f + 3 * T;
        // 12 independent, perfectly-coalesced LDG.128 (evict-first)
        float4 pa = __ldcs(p + f),  ta = __ldcs(t + f),  wa = __ldcs(w + f);
        float4 pb = __ldcs(p + f1), tb = __ldcs(t + f1), wb = __ldcs(w + f1);
        float4 pc = __ldcs(p + f2), tc = __ldcs(t + f2), wc = __ldcs(w + f2);
        float4 pd = __ldcs(p + f3), td = __ldcs(t + f3), wd = __ldcs(w + f3);

        #define SLOT(PV, TV, WV, FI) do {                                       \
            float _d0 = PV.x - TV.x, _d1 = PV.y - TV.y;                         \
            float _d2 = PV.z - TV.z, _d3 = PV.w - TV.w;                         \
            __half2 _h0 = __floats2half2_rn(WV.x*_d0*_d0, WV.y*_d1*_d1);        \
            __half2 _h1 = __floats2half2_rn(WV.z*_d2*_d2, WV.w*_d3*_d3);        \
            uint2 _o;                                                           \
            _o.x = *reinterpret_cast<unsigned*>(&_h0);                          \
            _o.y = *reinterpret_cast<unsigned*>(&_h1);                          \
            out[FI] = _o;                                                       \
            unsigned _m = __vmaxu2(_o.x, _o.y);                                 \
            unsigned _hm = max(_m & 0xFFFFu, _m >> 16);                         \
            _hm = max(_hm, __shfl_xor_sync(0xffffffffu, _hm, 1));               \
            _hm = max(_hm, __shfl_xor_sync(0xffffffffu, _hm, 2));               \
            if (qlead) g_gmax[(FI) >> 2] = (unsigned short)_hm;                 \
            if (samp)  atomicAdd(&hist[(_o.x & 0xFFFFu) >> 4], 1u);             \
        } while (0)

        SLOT(pa, ta, wa, f);
        SLOT(pb, tb, wb, f1);
        SLOT(pc, tc, wc, f2);
        SLOT(pd, td, wd, f3);
        #undef SLOT
    }
}

// ---------------------------------------------------------------- K2: threshold from sample
__global__ __launch_bounds__(1024) void k_select() {
    __shared__ unsigned ssum[1024];
    const int t = threadIdx.x;

    unsigned b0 = 0, b1 = 0, b2 = 0, b3 = 0;
    #pragma unroll
    for (int r = 0; r < NREP; r++) {
        uint4 v = reinterpret_cast<const uint4*>(g_shist[r])[t];
        b0 += v.x; b1 += v.y; b2 += v.z; b3 += v.w;
    }
    #pragma unroll
    for (int r = 0; r < NREP; r++)
        reinterpret_cast<uint4*>(g_shist[r])[t] = make_uint4(0, 0, 0, 0);

    ssum[t] = b0 + b1 + b2 + b3;
    __syncthreads();
    for (int d = 1; d < 1024; d <<= 1) {
        unsigned v = ssum[t];
        if (t + d < 1024) v += ssum[t + d];
        __syncthreads();
        ssum[t] = v;
        __syncthreads();
    }
    const unsigned TGT = (K_KEPT + MARGIN + 63u) / 64u;
    unsigned sufnext = (t < 1023) ? ssum[t + 1] : 0u;
    if (ssum[t] >= TGT && sufnext < TGT) {
        unsigned bins[4] = {b0, b1, b2, b3};
        unsigned cum = sufnext;
        unsigned T0 = 0;
        for (int b = 3; b >= 0; b--) {
            cum += bins[b];
            if (cum >= TGT) { T0 = ((unsigned)(t * 4 + b)) << 4; break; }
        }
        g_T0 = T0;
    }
}

// ---------------------------------------------------------------- K3: gmax-guided candidate histogram
__global__ __launch_bounds__(256) void k_scan() {
    const unsigned T0 = g_T0;
    const unsigned TT = T0 | (T0 << 16);
    const uint4* gm = reinterpret_cast<const uint4*>(g_gmax);
    const uint4* in = reinterpret_cast<const uint4*>(g_lossh);
    const int T = gridDim.x * blockDim.x;

    #define PROC_UNIT(v) do {                                                   \
        unsigned _m = __vcmpgeu2(__vmaxu2(__vmaxu2((v).x,(v).y),                \
                                          __vmaxu2((v).z,(v).w)), TT);          \
        if (_m) {                                                               \
            unsigned _h;                                                        \
            _h = (v).x & 0xFFFFu; if (_h >= T0) atomicAdd(&g_hist64[_h], 1u);   \
            _h = (v).x >> 16;     if (_h >= T0) atomicAdd(&g_hist64[_h], 1u);   \
            _h = (v).y & 0xFFFFu; if (_h >= T0) atomicAdd(&g_hist64[_h], 1u);   \
            _h = (v).y >> 16;     if (_h >= T0) atomicAdd(&g_hist64[_h], 1u);   \
            _h = (v).z & 0xFFFFu; if (_h >= T0) atomicAdd(&g_hist64[_h], 1u);   \
            _h = (v).z >> 16;     if (_h >= T0) atomicAdd(&g_hist64[_h], 1u);   \
            _h = (v).w & 0xFFFFu; if (_h >= T0) atomicAdd(&g_hist64[_h], 1u);   \
            _h = (v).w >> 16;     if (_h >= T0) atomicAdd(&g_hist64[_h], 1u);   \
        }                                                                       \
    } while (0)

    #define PROC_GROUP(g) do {                                                  \
        uint4 _a = in[2*(g)], _b = in[2*(g)+1];                                 \
        PROC_UNIT(_a); PROC_UNIT(_b);                                           \
    } while (0)

    #define PROC_GM(mv, idx) do {                                               \
        unsigned _mm = __vmaxu2(__vmaxu2((mv).x,(mv).y), __vmaxu2((mv).z,(mv).w)); \
        if (__vcmpgeu2(_mm, TT)) {                                              \
            int _g = 8*(idx);                                                   \
            if (((mv).x & 0xFFFFu) >= T0) PROC_GROUP(_g + 0);                   \
            if (((mv).x >> 16)     >= T0) PROC_GROUP(_g + 1);                   \
            if (((mv).y & 0xFFFFu) >= T0) PROC_GROUP(_g + 2);                   \
            if (((mv).y >> 16)     >= T0) PROC_GROUP(_g + 3);                   \
            if (((mv).z & 0xFFFFu) >= T0) PROC_GROUP(_g + 4);                   \
            if (((mv).z >> 16)     >= T0) PROC_GROUP(_g + 5);                   \
            if (((mv).w & 0xFFFFu) >= T0) PROC_GROUP(_g + 6);                   \
            if (((mv).w >> 16)     >= T0) PROC_GROUP(_g + 7);                   \
        }                                                                       \
    } while (0)

    for (int i = blockIdx.x * blockDim.x + threadIdx.x; i < NG4; i += 2 * T) {
        const int i2 = i + T;
        uint4 m0 = gm[i];
        uint4 m1;
        const bool h2v = (i2 < NG4);
        if (h2v) m1 = gm[i2];
        PROC_GM(m0, i);
        if (h2v) PROC_GM(m1, i2);
    }
    #undef PROC_GM
    #undef PROC_GROUP
    #undef PROC_UNIT
}

// ---------------------------------------------------------------- K4: fused tail (256 blocks, last-block finalize)
__global__ __launch_bounds__(256) void k_tail(float* __restrict__ out) {
    __shared__ unsigned swc[8];
    __shared__ float    sww[8];
    __shared__ bool     s_last;
    __shared__ unsigned sc[256];
    __shared__ float    sw[256];
    __shared__ int      s_chunk;
    __shared__ unsigned s_ac;
    __shared__ float    s_aw;
    const int t = threadIdx.x;
    const int bin = blockIdx.x * 256 + t;

    // chunk reduce: 1 bin/thread
    unsigned c = g_hist64[bin];
    float    v = c ? (float)c * bin_valf(bin) : 0.0f;
    unsigned cr = c; float vr = v;
    #pragma unroll
    for (int o = 16; o; o >>= 1) {
        cr += __shfl_down_sync(0xffffffffu, cr, o);
        vr += __shfl_down_sync(0xffffffffu, vr, o);
    }
    if ((t & 31) == 0) { swc[t >> 5] = cr; sww[t >> 5] = vr; }
    __syncthreads();
    if (t < 8) {
        unsigned cc = swc[t]; float vv = sww[t];
        #pragma unroll
        for (int o = 4; o; o >>= 1) {
            cc += __shfl_down_sync(0xffu, cc, o);
            vv += __shfl_down_sync(0xffu, vv, o);
        }
        if (t == 0) { g_ccnt[blockIdx.x] = cc; g_cwt[blockIdx.x] = vv; }
    }
    // last-block election
    if (t == 0) {
        __threadfence();
        s_last = (atomicAdd(&g_ticket, 1u) == 255u);
    }
    __syncthreads();
    if (!s_last) return;

    // ---- finalize (runs in exactly one block) ----
    sc[t] = g_ccnt[t];
    sw[t] = g_cwt[t];
    if (t == 0) s_chunk = -1;
    __syncthreads();
    for (int d = 1; d < 256; d <<= 1) {               // suffix scan over chunks
        unsigned cx = sc[t]; float xx = sw[t];
        if (t + d < 256) { cx += sc[t + d]; xx += sw[t + d]; }
        __syncthreads();
        sc[t] = cx; sw[t] = xx;
        __syncthreads();
    }
    unsigned cn = (t < 255) ? sc[t + 1] : 0u;
    float    wn = (t < 255) ? sw[t + 1] : 0.0f;
    if (sc[t] >= K_KEPT && cn < K_KEPT) { s_chunk = t; s_ac = cn; s_aw = wn; }
    __syncthreads();

    const int chunk = s_chunk;
    if (chunk < 0) {                                  // margin failure (~9-sigma; ~never)
        if (t == 0) {
            float acc = sw[0] + (float)(K_KEPT - sc[0]) * bin_valf((int)g_T0);
            out[0] = acc / 8796093022208.0f;          // / 2^43
        }
    } else {
        __syncthreads();
        unsigned bc = g_hist64[chunk * 256 + t];      // L2-hot
        sc[t] = bc;
        sw[t] = bc ? (float)bc * bin_valf(chunk * 256 + t) : 0.0f;
        __syncthreads();
        for (int d = 1; d < 256; d <<= 1) {           // suffix scan within chunk
            unsigned cx = sc[t]; float xx = sw[t];
            if (t + d < 256) { cx += sc[t + d]; xx += sw[t + d]; }
            __syncthreads();
            sc[t] = cx; sw[t] = xx;
            __syncthreads();
        }
        unsigned bn = (t < 255) ? sc[t + 1] : 0u;
        float    bw = (t < 255) ? sw[t + 1] : 0.0f;
        unsigned above = s_ac + bn;
        if (s_ac + sc[t] >= K_KEPT && above < K_KEPT) {
            unsigned r = K_KEPT - above;
            float acc = s_aw + bw + (float)r * bin_valf(chunk * 256 + t);
            out[0] = acc / 8796093022208.0f;          // / (2^25 * 2^18)
        }
    }
    __syncthreads();
    // zero dirty hist range [T0, 65536) + reset ticket for next replay
    uint4 z = make_uint4(0, 0, 0, 0);
    for (unsigned idx = (g_T0 >> 2) + t; idx < 16384u; idx += 256u)
        reinterpret_cast<uint4*>(g_hist64)[idx] = z;
    if (t == 0) g_ticket = 0u;
}

// ---------------------------------------------------------------- launch
extern "C" void kernel_launch(void* const* d_in, const int* in_sizes, int n_in,
                              void* d_out, int out_size) {
    const float4* p = (const float4*)d_in[0];   // predict
    const float4* t = (const float4*)d_in[1];   // target
    const float4* w = (const float4*)d_in[2];   // weight
    float* out = (float*)d_out;

    k_loss  <<<1024, 256>>>(p, t, w);   // grid MUST stay 1024 (uniform trips)
    k_select<<<1, 1024>>>();
    k_scan  <<<512, 256>>>();
    k_tail  <<<256, 256>>>(out);
}

// round 7
// speedup vs baseline: 1.7417x; 1.0991x over previous
#include <cuda_runtime.h>
#include <cuda_fp16.h>

// OhemMSELoss: loss = w*(p-t)^2 / 2^25 over N=2^25; mean of top-k (k=2^18).
// K1: coalesced stream; computes loss (fp16 bits) but stores ONLY a per-16-elem
//     group-max skip index (4 MB) + 1/64-sampled histogram. Also zeroes g_hist64
//     (parallel prologue). No 64 MB scratch write.
// K2: conservative threshold T0 from sample (~9-sigma margin).
// K3: scan skip index; RECOMPUTE loss for candidate groups only (~13%);
//     exact 65536-bin histogram of candidate elements (~300K atomics).
//     Bit-identical recompute: loss expr is sub+mul+mul (no FMA contraction).
// K4: 256 blocks reduce chunks -> last block (ticket) finalizes. All fp32.

#define N_ELEM   33554432
#define N4       (N_ELEM / 4)       // 8388608 float4 per stream
#define N16      (N_ELEM / 16)      // 2097152 groups
#define NG4      (N16 / 8)          // 262144 uint4 units of gmax index
#define K_KEPT   262144u
#define MARGIN   40960u
#define NSB      4096
#define NREP     8

static __device__ unsigned short g_gmax[N16];         // 4 MiB skip index
static __device__ unsigned       g_shist[NREP][NSB];  // zero-init; cleaned by K2
static __device__ unsigned       g_hist64[65536];     // zeroed by K1 prologue
static __device__ unsigned       g_T0;
static __device__ unsigned       g_ccnt[256];
static __device__ float          g_cwt[256];
static __device__ unsigned       g_ticket;            // zero-init; reset by K4

__device__ __forceinline__ float bin_valf(int b) {
    return __half2float(__ushort_as_half((unsigned short)b));
}

// Deterministic loss for 4 elems -> 4 fp16 bit patterns (2 packed words).
// ONLY sub/mul ops -> no FMA contraction -> identical bits in K1 and K3.
__device__ __forceinline__ uint2 loss4(float4 pv, float4 tv, float4 wv) {
    float d0 = pv.x - tv.x, d1 = pv.y - tv.y;
    float d2 = pv.z - tv.z, d3 = pv.w - tv.w;
    __half2 h0 = __floats2half2_rn(wv.x * d0 * d0, wv.y * d1 * d1);
    __half2 h1 = __floats2half2_rn(wv.z * d2 * d2, wv.w * d3 * d3);
    uint2 o;
    o.x = *reinterpret_cast<unsigned*>(&h0);
    o.y = *reinterpret_cast<unsigned*>(&h1);
    return o;
}

// ---------------------------------------------------------------- K1
// grid MUST be 1024 x 256: N4 / (4*T) == 8 exactly -> uniform trips (shfl-safe),
// lane-consecutive float4 indices -> perfect coalescing.
__global__ __launch_bounds__(256) void k_loss(
    const float4* __restrict__ p,
    const float4* __restrict__ t,
    const float4* __restrict__ w)
{
    // parallel hist64 zeroing, hidden behind the streaming work
    if (blockIdx.x < 64)
        reinterpret_cast<uint4*>(g_hist64)[blockIdx.x * 256 + threadIdx.x] =
            make_uint4(0, 0, 0, 0);

    unsigned* hist = g_shist[blockIdx.x & (NREP - 1)];
    const int T = gridDim.x * blockDim.x;             // 262144
    const int lane = threadIdx.x & 31;
    const bool qlead = ((lane & 3) == 0);
    const bool samp  = ((threadIdx.x & 15) == 0);     // 1/64-element sampling

    for (int f = blockIdx.x * blockDim.x + threadIdx.x; f < N4; f += 4 * T) {
        const int f1 = f + T, f2 = f + 2 * T, f3 = f + 3 * T;
        // 12 independent, perfectly-coalesced LDG.128 (evict-first)
        float4 pa = __ldcs(p + f),  ta = __ldcs(t + f),  wa = __ldcs(w + f);
        float4 pb = __ldcs(p + f1), tb = __ldcs(t + f1), wb = __ldcs(w + f1);
        float4 pc = __ldcs(p + f2), tc = __ldcs(t + f2), wc = __ldcs(w + f2);
        float4 pd = __ldcs(p + f3), td = __ldcs(t + f3), wd = __ldcs(w + f3);

        #define SLOT(PV, TV, WV, FI) do {                                       \
            uint2 _o = loss4(PV, TV, WV);                                       \
            unsigned _m = __vmaxu2(_o.x, _o.y);                                 \
            unsigned _hm = max(_m & 0xFFFFu, _m >> 16);                         \
            _hm = max(_hm, __shfl_xor_sync(0xffffffffu, _hm, 1));               \
            _hm = max(_hm, __shfl_xor_sync(0xffffffffu, _hm, 2));               \
            if (qlead) g_gmax[(FI) >> 2] = (unsigned short)_hm;                 \
            if (samp)  atomicAdd(&hist[(_o.x & 0xFFFFu) >> 4], 1u);             \
        } while (0)

        SLOT(pa, ta, wa, f);
        SLOT(pb, tb, wb, f1);
        SLOT(pc, tc, wc, f2);
        SLOT(pd, td, wd, f3);
        #undef SLOT
    }
}

// ---------------------------------------------------------------- K2: threshold from sample
__global__ __launch_bounds__(1024) void k_select() {
    __shared__ unsigned ssum[1024];
    const int t = threadIdx.x;

    unsigned b0 = 0, b1 = 0, b2 = 0, b3 = 0;
    #pragma unroll
    for (int r = 0; r < NREP; r++) {
        uint4 v = reinterpret_cast<const uint4*>(g_shist[r])[t];
        b0 += v.x; b1 += v.y; b2 += v.z; b3 += v.w;
    }
    #pragma unroll
    for (int r = 0; r < NREP; r++)
        reinterpret_cast<uint4*>(g_shist[r])[t] = make_uint4(0, 0, 0, 0);

    ssum[t] = b0 + b1 + b2 + b3;
    __syncthreads();
    for (int d = 1; d < 1024; d <<= 1) {
        unsigned v = ssum[t];
        if (t + d < 1024) v += ssum[t + d];
        __syncthreads();
        ssum[t] = v;
        __syncthreads();
    }
    const unsigned TGT = (K_KEPT + MARGIN + 63u) / 64u;
    unsigned sufnext = (t < 1023) ? ssum[t + 1] : 0u;
    if (ssum[t] >= TGT && sufnext < TGT) {
        unsigned bins[4] = {b0, b1, b2, b3};
        unsigned cum = sufnext;
        unsigned T0 = 0;
        for (int b = 3; b >= 0; b--) {
            cum += bins[b];
            if (cum >= TGT) { T0 = ((unsigned)(t * 4 + b)) << 4; break; }
        }
        g_T0 = T0;
    }
}

// ---------------------------------------------------------------- K3: gmax-guided recompute + candidate hist
__global__ __launch_bounds__(256) void k_scan(
    const float4* __restrict__ p,
    const float4* __restrict__ t,
    const float4* __restrict__ w)
{
    const unsigned thr = g_T0;
    const unsigned TT  = thr | (thr << 16);
    const uint4* gm = reinterpret_cast<const uint4*>(g_gmax);
    const int T = gridDim.x * blockDim.x;

    #define TEST2(word) do {                                                    \
        unsigned _h;                                                            \
        _h = (word) & 0xFFFFu; if (_h >= thr) atomicAdd(&g_hist64[_h], 1u);     \
        _h = (word) >> 16;     if (_h >= thr) atomicAdd(&g_hist64[_h], 1u);     \
    } while (0)

    #define PROC_GROUP(g) do {                                                  \
        const int _fb = 4 * (g);                                                \
        float4 _p0 = __ldg(p + _fb),     _t0 = __ldg(t + _fb),     _w0 = __ldg(w + _fb);     \
        float4 _p1 = __ldg(p + _fb + 1), _t1 = __ldg(t + _fb + 1), _w1 = __ldg(w + _fb + 1); \
        float4 _p2 = __ldg(p + _fb + 2), _t2 = __ldg(t + _fb + 2), _w2 = __ldg(w + _fb + 2); \
        float4 _p3 = __ldg(p + _fb + 3), _t3 = __ldg(t + _fb + 3), _w3 = __ldg(w + _fb + 3); \
        uint2 _a = loss4(_p0, _t0, _w0);                                        \
        uint2 _b = loss4(_p1, _t1, _w1);                                        \
        uint2 _c = loss4(_p2, _t2, _w2);                                        \
        uint2 _d = loss4(_p3, _t3, _w3);                                        \
        TEST2(_a.x); TEST2(_a.y); TEST2(_b.x); TEST2(_b.y);                     \
        TEST2(_c.x); TEST2(_c.y); TEST2(_d.x); TEST2(_d.y);                     \
    } while (0)

    #define PROC_GM(mv, idx) do {                                               \
        unsigned _mm = __vmaxu2(__vmaxu2((mv).x,(mv).y), __vmaxu2((mv).z,(mv).w)); \
        if (__vcmpgeu2(_mm, TT)) {                                              \
            int _g = 8*(idx);                                                   \
            if (((mv).x & 0xFFFFu) >= thr) PROC_GROUP(_g + 0);                  \
            if (((mv).x >> 16)     >= thr) PROC_GROUP(_g + 1);                  \
            if (((mv).y & 0xFFFFu) >= thr) PROC_GROUP(_g + 2);                  \
            if (((mv).y >> 16)     >= thr) PROC_GROUP(_g + 3);                  \
            if (((mv).z & 0xFFFFu) >= thr) PROC_GROUP(_g + 4);                  \
            if (((mv).z >> 16)     >= thr) PROC_GROUP(_g + 5);                  \
            if (((mv).w & 0xFFFFu) >= thr) PROC_GROUP(_g + 6);                  \
            if (((mv).w >> 16)     >= thr) PROC_GROUP(_g + 7);                  \
        }                                                                       \
    } while (0)

    for (int i = blockIdx.x * blockDim.x + threadIdx.x; i < NG4; i += 2 * T) {
        const int i2 = i + T;
        uint4 m0 = gm[i];
        uint4 m1;
        const bool h2v = (i2 < NG4);
        if (h2v) m1 = gm[i2];
        PROC_GM(m0, i);
        if (h2v) PROC_GM(m1, i2);
    }
    #undef PROC_GM
    #undef PROC_GROUP
    #undef TEST2
}

// ---------------------------------------------------------------- K4: tail (256 blocks, last-block finalize)
__global__ __launch_bounds__(256) void k_tail(float* __restrict__ out) {
    __shared__ unsigned swc[8];
    __shared__ float    sww[8];
    __shared__ bool     s_last;
    __shared__ unsigned sc[256];
    __shared__ float    sw[256];
    __shared__ int      s_chunk;
    __shared__ unsigned s_ac;
    __shared__ float    s_aw;
    const int t = threadIdx.x;
    const int bin = blockIdx.x * 256 + t;

    unsigned c = g_hist64[bin];
    float    v = c ? (float)c * bin_valf(bin) : 0.0f;
    unsigned cr = c; float vr = v;
    #pragma unroll
    for (int o = 16; o; o >>= 1) {
        cr += __shfl_down_sync(0xffffffffu, cr, o);
        vr += __shfl_down_sync(0xffffffffu, vr, o);
    }
    if ((t & 31) == 0) { swc[t >> 5] = cr; sww[t >> 5] = vr; }
    __syncthreads();
    if (t < 8) {
        unsigned cc = swc[t]; float vv = sww[t];
        #pragma unroll
        for (int o = 4; o; o >>= 1) {
            cc += __shfl_down_sync(0xffu, cc, o);
            vv += __shfl_down_sync(0xffu, vv, o);
        }
        if (t == 0) { g_ccnt[blockIdx.x] = cc; g_cwt[blockIdx.x] = vv; }
    }
    if (t == 0) {
        __threadfence();
        s_last = (atomicAdd(&g_ticket, 1u) == 255u);
    }
    __syncthreads();
    if (!s_last) return;

    // ---- finalize (exactly one block) ----
    sc[t] = g_ccnt[t];
    sw[t] = g_cwt[t];
    if (t == 0) s_chunk = -1;
    __syncthreads();
    for (int d = 1; d < 256; d <<= 1) {               // suffix scan over chunks
        unsigned cx = sc[t]; float xx = sw[t];
        if (t + d < 256) { cx += sc[t + d]; xx += sw[t + d]; }
        __syncthreads();
        sc[t] = cx; sw[t] = xx;
        __syncthreads();
    }
    unsigned cn = (t < 255) ? sc[t + 1] : 0u;
    float    wn = (t < 255) ? sw[t + 1] : 0.0f;
    if (sc[t] >= K_KEPT && cn < K_KEPT) { s_chunk = t; s_ac = cn; s_aw = wn; }
    __syncthreads();

    const int chunk = s_chunk;
    if (chunk < 0) {                                  // margin failure (~9-sigma; ~never)
        if (t == 0) {
            float acc = sw[0] + (float)(K_KEPT - sc[0]) * bin_valf((int)g_T0);
            out[0] = acc / 8796093022208.0f;          // / 2^43
        }
    } else {
        __syncthreads();
        unsigned bc = g_hist64[chunk * 256 + t];      // L2-hot
        sc[t] = bc;
        sw[t] = bc ? (float)bc * bin_valf(chunk * 256 + t) : 0.0f;
        __syncthreads();
        for (int d = 1; d < 256; d <<= 1) {           // suffix scan within chunk
            unsigned cx = sc[t]; float xx = sw[t];
            if (t + d < 256) { cx += sc[t + d]; xx += sw[t + d]; }
            __syncthreads();
            sc[t] = cx; sw[t] = xx;
            __syncthreads();
        }
        unsigned bn = (t < 255) ? sc[t + 1] : 0u;
        float    bw = (t < 255) ? sw[t + 1] : 0.0f;
        unsigned above = s_ac + bn;
        if (s_ac + sc[t] >= K_KEPT && above < K_KEPT) {
            unsigned r = K_KEPT - above;
            float acc = s_aw + bw + (float)r * bin_valf(chunk * 256 + t);
            out[0] = acc / 8796093022208.0f;          // / (2^25 * 2^18)
        }
    }
    __syncthreads();
    if (t == 0) g_ticket = 0u;                        // reset for next replay
}

// ---------------------------------------------------------------- launch
extern "C" void kernel_launch(void* const* d_in, const int* in_sizes, int n_in,
                              void* d_out, int out_size) {
    const float4* p = (const float4*)d_in[0];   // predict
    const float4* t = (const float4*)d_in[1];   // target
    const float4* w = (const float4*)d_in[2];   // weight
    float* out = (float*)d_out;

    k_loss  <<<1024, 256>>>(p, t, w);   // grid MUST stay 1024 (uniform trips)
    k_select<<<1, 1024>>>();
    k_scan  <<<512, 256>>>(p, t, w);
    k_tail  <<<256, 256>>>(out);
}